// round 11
// baseline (speedup 1.0000x reference)
#include <cuda_runtime.h>
#include <math_constants.h>

// ProgressReward — round 10: payload-carrying atomic argmin.
//
// Block i owns static polyline chunk [c0,c1). Phase 1 (one global sync):
//   producer (warp 15): cycle-0 loads poly_batch[ends] AND an agent_ptr
//     window around the expected batch c0*B/P (+-2); stages per-query
//     (qx,qy,dqx,dqy) where dq = q_cur - q_pre.
//   stage (warps 0-14): cycle-0 loads candidates AND the int32 mask into
//     smem; bar.sync(1,STG); writes s4 (c,s,a|+INF,bv) + batch bounds s_bnd.
// Eval: 8 groups x 64 queries scan candidate slices tracking (best,idx);
// after the loop the winner's contribution prog = c*dqx + s*dqy is computed
// from smem and published with ONE atomicMax(g_win, ~packed) per group,
// packed = (dist_bits<<32) | fp32(prog)_bits. Unsigned min == min dist
// (exact dist ties are measure-zero in this data; payload order irrelevant).
// Grid spin barrier (single wave, grid<=148). Phase 2: block b<B reads its
// 64 winners (one L2 RT), unpacks prog directly, shfl-sums per role, writes
// out[b] = min(max(pE,2)/max(pX,2),1), resets its g_win words. Zero-init +
// complement packing + resets => CUDA-graph replay safe.

#define NUM_HIST 4
#define INTERVAL 5
#define IP_ROWS  36
#define L_ROWS   180
#define TPB      512
#define STG      480
#define SUBCH    480
#define QS       8
#define B_MAX    256
#define MASK_SM  2048

__device__ unsigned long long g_win[B_MAX * 64];   // zero-init; self-resetting
__device__ int g_sync1, g_sync2;                   // zero-init; self-resetting

__global__ void __launch_bounds__(TPB)
progress_reward_kernel(
    const int*   __restrict__ poly_batch,
    const float* __restrict__ poly_pos,
    const float* __restrict__ poly_heading,
    const int*   __restrict__ edge_index,
    const int*   __restrict__ on_route_mask,
    const int*   __restrict__ agent_ptr,
    const float* __restrict__ infer_pos,
    const int*   __restrict__ agent_batch,         // unused (CSR invariant)
    const float* __restrict__ agent_pos,
    float*       __restrict__ out,
    int P, int NG, int B)
{
    __shared__ float4 s4[SUBCH];
    __shared__ int    s_mask[MASK_SM];
    __shared__ int    s_bnd[B_MAX + 2];
    __shared__ float4 s_q[QS][64];                 // (qx,qy,dqx,dqy)
    __shared__ int    s_b0, s_b1;
    __shared__ int    s_aidx[QS];
    __shared__ float  s_sum[2];

    const int grid = gridDim.x;
    const int bi   = blockIdx.x;
    const int tid  = threadIdx.x;
    const int lane = tid & 31;
    const int warp = tid >> 5;
    const int g    = tid >> 6;                     // 0..7
    const int sub  = tid & 63;
    const int role = sub >> 5;
    const int t    = sub & 31;

    const int chunk = (P + grid - 1) / grid;
    const int c0 = bi * chunk;
    const int c1 = min(c0 + chunk, P);
    const bool useSM = (NG <= MASK_SM);

    const float2* pp2 = (const float2*)poly_pos;

    // ================= phase 1 =================
    for (int base = c0; base < c1; base += SUBCH) {
        const int cnt = min(SUBCH, c1 - base);

        if (warp == 15) {
            // ---- producer: window prefetch + span + query staging ----
            int w0 = (int)(((long long)c0 * B) / P) - 2;
            if (w0 > B - 8) w0 = B - 8;
            if (w0 < 0) w0 = 0;
            int apw = 0;
            if (lane < 8 && (w0 + lane) <= B) apw = agent_ptr[w0 + lane];
            int e = 0;
            if (lane == 0) e = poly_batch[base];
            if (lane == 1) e = poly_batch[base + cnt - 1];
            const int sb0 = __shfl_sync(0xFFFFFFFFu, e, 0);
            const int sb1 = __shfl_sync(0xFFFFFFFFu, e, 1);
            if (lane == 0) { s_b0 = sb0; s_b1 = sb1; }
            if (lane == 2) s_bnd[sb1 + 1] = cnt;
            const int nq = min(sb1 - sb0 + 1, QS);
            int ax = 0;
            if ((sb0 >= w0) && (sb0 + nq - 1 <= w0 + 7)) {
                const int src = sb0 - w0 + lane;
                ax = __shfl_sync(0xFFFFFFFFu, apw, src & 31);
            } else if (lane < nq) {
                ax = agent_ptr[sb0 + lane];                    // rare fallback
            }
            for (int k = 0; k < nq; k++) {
                const int a = __shfl_sync(0xFFFFFFFFu, ax, k);
                const float2* ip = (const float2*)(infer_pos + (size_t)a * (IP_ROWS * 2));
                float2 qc2 = ip[NUM_HIST + lane];
                float2 qp2 = ip[NUM_HIST - 1 + lane];
                s_q[k][lane] = make_float4(qc2.x, qc2.y,
                                           qc2.x - qp2.x, qc2.y - qp2.y);
                const float2* ap = (const float2*)(agent_pos + (size_t)a * (L_ROWS * 2));
                qc2 = ap[(4 + lane) * INTERVAL];
                qp2 = ap[(3 + lane) * INTERVAL];
                s_q[k][32 + lane] = make_float4(qc2.x, qc2.y,
                                                qc2.x - qp2.x, qc2.y - qp2.y);
            }
        } else {
            // ---- stage: all global loads issued before the named barrier ----
            int   v = 0, vp = 0, poly = 0;
            float ch = 0.f, sh = 0.f, a = 0.f, bv = 0.f;
            const bool have = (tid < cnt);
            if (have) {
                const int p = base + tid;
                v    = poly_batch[p];
                vp   = (tid > 0) ? poly_batch[p - 1] : v;
                poly = edge_index[P + p];
                const float2 pos = pp2[p];
                const float h = poly_heading[p];
                ch = cosf(h);
                sh = sinf(h);
                a  = fmaf(ch, pos.x, sh * pos.y);
                bv = fmaf(ch, pos.y, -sh * pos.x);
            }
            if (useSM)
                for (int i = tid; i < NG; i += STG) s_mask[i] = on_route_mask[i];
            asm volatile("bar.sync 1, %0;" :: "r"(STG) : "memory");
            if (have) {
                const int on = useSM ? s_mask[poly] : on_route_mask[poly];
                float4 w;
                w.x = ch; w.y = sh;
                w.z = on ? a : CUDART_INF_F;
                w.w = bv;
                s4[tid] = w;
                if (tid == 0) s_bnd[v] = 0;
                else
                    for (int b2 = vp + 1; b2 <= v; b2++) s_bnd[b2] = tid;
            }
        }
        __syncthreads();

        const int sb0 = s_b0;
        const int sb1 = s_b1;

        for (int bq = sb0; bq <= sb1; bq += QS) {
            const int nqw = min(QS, sb1 - bq + 1);

            if (bq != sb0) {
                // rare: span wider than QS batches -> restage queries
                __syncthreads();
                if (tid < nqw) s_aidx[tid] = agent_ptr[bq + tid];
                __syncthreads();
                if (tid < nqw * 64) {
                    const int k  = tid >> 6;
                    const int qs = tid & 63;
                    const int qr = qs >> 5, qt = qs & 31;
                    const int a  = s_aidx[k];
                    float2 qc2, qp2;
                    if (qr == 0) {
                        const float2* ip = (const float2*)(infer_pos + (size_t)a * (IP_ROWS * 2));
                        qc2 = ip[NUM_HIST + qt];
                        qp2 = ip[NUM_HIST - 1 + qt];
                    } else {
                        const float2* ap = (const float2*)(agent_pos + (size_t)a * (L_ROWS * 2));
                        qc2 = ap[(4 + qt) * INTERVAL];
                        qp2 = ap[(3 + qt) * INTERVAL];
                    }
                    s_q[k][qs] = make_float4(qc2.x, qc2.y,
                                             qc2.x - qp2.x, qc2.y - qp2.y);
                }
                __syncthreads();
            }

            for (int k = 0; k < nqw; k++) {
                const int bb = bq + k;
                const int r0 = s_bnd[bb];
                const int r1 = s_bnd[bb + 1];
                const int m  = r1 - r0;
                if (m <= 0) continue;

                const float4 q = s_q[k][sub];
                float best = CUDART_INF_F;
                int   bil  = 0;
                const int slice = (m + 7) >> 3;
                const int i0 = r0 + g * slice;
                const int i1 = min(i0 + slice, r1);
                #pragma unroll 4
                for (int i = i0; i < i1; i++) {
                    const float4 v = s4[i];
                    const float x = fmaf(v.x, q.x, fmaf(v.y, q.y, -v.z));
                    const float y = fmaf(v.x, q.y, -fmaf(v.y, q.x, v.w));
                    float d = fmaf(fabsf(y), 10.0f, fabsf(x));
                    if (x > 0.0f) d += 1000.0f;
                    if (d < best) { best = d; bil = i; }
                }
                if (best < CUDART_INF_F) {
                    const float4 v = s4[bil];
                    const float prog = fmaf(v.x, q.z, v.y * q.w);  // c*dqx+s*dqy
                    const unsigned long long pk =
                        ((unsigned long long)__float_as_uint(best) << 32)
                        | __float_as_uint(prog);
                    atomicMax(&g_win[bb * 64 + sub], ~pk);
                }
            }
        }
        __syncthreads();
    }

    // ================= grid barrier =================
    __threadfence();
    if (tid == 0) {
        atomicAdd(&g_sync1, 1);
        while (*(volatile int*)&g_sync1 < grid) { }
    }
    __syncthreads();
    __threadfence();

    // ================= phase 2: one L2 RT, payload IS the answer ==========
    if (bi < B && tid < 64) {
        const unsigned long long w = ~g_win[bi * 64 + tid];
        g_win[bi * 64 + tid] = 0;                  // reset for next replay
        float prog = 0.0f;
        if ((unsigned)(w >> 32) < 0x7F800000u)     // finite best dist
            prog = __uint_as_float((unsigned)w);
        #pragma unroll
        for (int o = 16; o > 0; o >>= 1)
            prog += __shfl_down_sync(0xFFFFFFFFu, prog, o);
        if (t == 0) s_sum[role] = prog;
    }
    __syncthreads();
    if (bi < B && tid == 0)
        out[bi] = fminf(fmaxf(s_sum[0], 2.0f) / fmaxf(s_sum[1], 2.0f), 1.0f);

    if (tid == 0) {
        if (atomicAdd(&g_sync2, 1) == grid - 1) {
            g_sync1 = 0;
            g_sync2 = 0;
        }
    }
}

extern "C" void kernel_launch(void* const* d_in, const int* in_sizes, int n_in,
                              void* d_out, int out_size)
{
    const int*   poly_batch    = (const int*)  d_in[0];
    const float* poly_pos      = (const float*)d_in[1];
    const float* poly_heading  = (const float*)d_in[2];
    const int*   edge_index    = (const int*)  d_in[3];
    const int*   on_route_mask = (const int*)  d_in[4];
    const int*   agent_ptr     = (const int*)  d_in[5];
    const float* infer_pos     = (const float*)d_in[6];
    const int*   agent_batch   = (const int*)  d_in[7];
    const float* agent_pos     = (const float*)d_in[8];
    float*       out           = (float*)      d_out;

    const int P  = in_sizes[0];
    const int NG = in_sizes[4];
    int B        = in_sizes[5] - 1;
    if (B > B_MAX) B = B_MAX;

    int grid = 128;                            // single wave for spin barrier
    if (B > grid) grid = (B <= 148) ? B : 148;

    progress_reward_kernel<<<grid, TPB>>>(
        poly_batch, poly_pos, poly_heading, edge_index, on_route_mask,
        agent_ptr, infer_pos, agent_batch, agent_pos, out, P, NG, B);
}

// round 12
// speedup vs baseline: 1.0030x; 1.0030x over previous
#include <cuda_runtime.h>
#include <math_constants.h>

// ProgressReward — round 11: no global barrier; per-batch completion counters
// + speculative query prefetch.
//
// Block i owns static polyline chunk [c0,c1).
//  - All threads speculatively prefetch queries for an 8-batch window around
//    the expected batch c0*B/P, guessing agent_ptr[b] = b*agents_per; the
//    producer warp validates against the real agent_ptr (fallback restage on
//    mismatch). Queries stored as (qx,qy,dqx,dqy).
//  - Stage warps (0-14) load candidates + int32 mask (smem) and write s4 =
//    (c,s,a|+INF off-route, bv) + local batch bounds s_bnd. The thread at a
//    global sorted transition into batch w also writes g_lo[w]=p+1
//    (REPLAY-INVARIANT value -> never reset; stale==fresh).
//  - Eval: 8 groups x 64 queries track (best,idx); winner's contribution
//    prog = c*dqx + s*dqy published via atomicMax(g_win, ~packed),
//    packed=(dist_bits<<32)|prog_bits (unsigned min == min dist; exact dist
//    ties measure-zero).
//  - Completion: per-thread __threadfence, __syncthreads, then warp 0 does
//    atomicAdd(g_fin[bb],1) for each batch with local elements (last-touch
//    gated for multi-sub-chunk generality).
//  - Phase 2 (block b<B): poll g_lo[b], g_lo[b+1] (nonzero sentinels),
//    compute exact participant count from the static chunk map, poll
//    g_fin[b] >= n, acquire-fence, read 64 winners (one L2 RT), shfl-sum,
//    out[b]=min(max(pE,2)/max(pX,2),1). Resets g_fin[b] and its g_win words.

#define NUM_HIST 4
#define INTERVAL 5
#define IP_ROWS  36
#define L_ROWS   180
#define TPB      512
#define STG      480
#define SUBCH    480
#define QS       8
#define B_MAX    256
#define MASK_SM  2048

__device__ unsigned long long g_win[B_MAX * 64];   // zero-init; self-resetting
__device__ int g_fin[B_MAX];                       // zero-init; self-resetting
__device__ int g_lo[B_MAX + 2];                    // lo+1; replay-invariant

__global__ void __launch_bounds__(TPB)
progress_reward_kernel(
    const int*   __restrict__ poly_batch,
    const float* __restrict__ poly_pos,
    const float* __restrict__ poly_heading,
    const int*   __restrict__ edge_index,
    const int*   __restrict__ on_route_mask,
    const int*   __restrict__ agent_ptr,
    const float* __restrict__ infer_pos,
    const int*   __restrict__ agent_batch,         // unused (CSR invariant)
    const float* __restrict__ agent_pos,
    float*       __restrict__ out,
    int P, int NG, int B, int agents_per)
{
    __shared__ float4 s4[SUBCH];
    __shared__ int    s_mask[MASK_SM];
    __shared__ int    s_bnd[B_MAX + 2];
    __shared__ float4 s_q[QS][64];                 // (qx,qy,dqx,dqy)
    __shared__ int    s_b0, s_b1, s_nextb, s_qb, s_dstr;
    __shared__ int    s_aidx[QS];
    __shared__ float  s_sum[2];

    const int grid = gridDim.x;
    const int bi   = blockIdx.x;
    const int tid  = threadIdx.x;
    const int lane = tid & 31;
    const int warp = tid >> 5;
    const int g    = tid >> 6;
    const int sub  = tid & 63;
    const int role = sub >> 5;
    const int t    = sub & 31;

    const int chunk = (P + grid - 1) / grid;
    const int c0 = bi * chunk;
    const int c1 = min(c0 + chunk, P);
    const bool useSM = (NG <= MASK_SM);

    if (tid == 0) s_dstr = 0;

    // window base around expected batch (pure ALU, no loads)
    int w0 = (int)(((long long)c0 * B) / P) - 2;
    if (w0 > B - 8) w0 = B - 8;
    if (w0 < 0) w0 = 0;

    // ---- speculative query prefetch (all threads, cycle 0) ----
    {
        const int k = g;                           // window slot 0..7
        if (w0 + k < B) {
            const int ga = (w0 + k) * agents_per;  // guessed agent_ptr
            float2 a2, b2;
            if (role == 0) {
                const float2* ip = (const float2*)(infer_pos + (size_t)ga * (IP_ROWS * 2));
                a2 = ip[NUM_HIST + t];
                b2 = ip[NUM_HIST - 1 + t];
            } else {
                const float2* ap = (const float2*)(agent_pos + (size_t)ga * (L_ROWS * 2));
                a2 = ap[(4 + t) * INTERVAL];
                b2 = ap[(3 + t) * INTERVAL];
            }
            s_q[k][sub] = make_float4(a2.x, a2.y, a2.x - b2.x, a2.y - b2.y);
        }
    }

    const float2* pp2 = (const float2*)poly_pos;

    auto evalBatches = [&](int b0, int b1, int qb0, int base) {
        for (int bb = b0; bb <= b1; bb++) {
            const int kq = bb - qb0;
            if (kq < 0 || kq >= QS) continue;
            const int r0 = s_bnd[bb];
            const int r1 = s_bnd[bb + 1];
            const int m  = r1 - r0;
            if (m <= 0) continue;
            const float4 q = s_q[kq][sub];
            float best = CUDART_INF_F;
            int   bil  = 0;
            const int slice = (m + 7) >> 3;
            const int i0 = r0 + g * slice;
            const int i1 = min(i0 + slice, r1);
            #pragma unroll 4
            for (int i = i0; i < i1; i++) {
                const float4 v = s4[i];
                const float x = fmaf(v.x, q.x, fmaf(v.y, q.y, -v.z));
                const float y = fmaf(v.x, q.y, -fmaf(v.y, q.x, v.w));
                float d = fmaf(fabsf(y), 10.0f, fabsf(x));
                if (x > 0.0f) d += 1000.0f;
                if (d < best) { best = d; bil = i; }
            }
            if (best < CUDART_INF_F) {
                const float4 v = s4[bil];
                const float prog = fmaf(v.x, q.z, v.y * q.w);
                const unsigned long long pk =
                    ((unsigned long long)__float_as_uint(best) << 32)
                    | __float_as_uint(prog);
                atomicMax(&g_win[bb * 64 + sub], ~pk);
            }
        }
    };

    // ================= phase 1 =================
    for (int base = c0; base < c1; base += SUBCH) {
        const int cnt = min(SUBCH, c1 - base);

        if (warp == 15) {
            // ---- producer: window validate + span (1 chained RT) ----
            int apw = 0;
            if (lane < 8 && (w0 + lane) <= B) apw = agent_ptr[w0 + lane];
            int e = 0;
            if (lane == 0) e = poly_batch[base];
            if (lane == 1) e = poly_batch[base + cnt - 1];
            if (lane == 2) e = (base + cnt < P) ? poly_batch[base + cnt] : 0x7FFFFFFF;
            const int sb0 = __shfl_sync(0xFFFFFFFFu, e, 0);
            const int sb1 = __shfl_sync(0xFFFFFFFFu, e, 1);
            const int nxb = __shfl_sync(0xFFFFFFFFu, e, 2);
            bool vok = true;
            if (lane < 8 && (w0 + lane) < B)
                vok = (apw == (w0 + lane) * agents_per);
            const unsigned msk = __ballot_sync(0xFFFFFFFFu, vok);
            const bool winok = ((msk & 0xFFu) == 0xFFu);
            if (lane == 0) {
                s_b0 = sb0; s_b1 = sb1; s_nextb = nxb;
                const bool intact = (base == c0) || (s_dstr == 0);
                s_qb = (winok && intact && sb0 >= w0 && sb1 <= w0 + 7) ? w0 : -1;
            }
            if (lane == 3) s_bnd[sb1 + 1] = cnt;
        } else {
            // ---- stage: candidates + mask; publish g_lo at transitions ----
            int   v = 0, vp = -1, poly = 0;
            float ch = 0.f, sh = 0.f, a = 0.f, bv = 0.f;
            const bool have = (tid < cnt);
            int p = base + tid;
            if (have) {
                v    = poly_batch[p];
                vp   = (p > 0) ? poly_batch[p - 1] : -1;
                poly = edge_index[P + p];
                const float2 pos = pp2[p];
                const float h = poly_heading[p];
                ch = cosf(h);
                sh = sinf(h);
                a  = fmaf(ch, pos.x, sh * pos.y);
                bv = fmaf(ch, pos.y, -sh * pos.x);
            }
            if (useSM)
                for (int i = tid; i < NG; i += STG) s_mask[i] = on_route_mask[i];
            asm volatile("bar.sync 1, %0;" :: "r"(STG) : "memory");
            if (have) {
                const int on = useSM ? s_mask[poly] : on_route_mask[poly];
                float4 w;
                w.x = ch; w.y = sh;
                w.z = on ? a : CUDART_INF_F;
                w.w = bv;
                s4[tid] = w;
                // local batch bounds
                if (tid == 0) s_bnd[v] = 0;
                else
                    for (int b2 = vp + 1; b2 <= v; b2++) s_bnd[b2] = tid;
                // global transitions -> g_lo (replay-invariant; plain store)
                if (vp < v)
                    for (int w2 = vp + 1; w2 <= v; w2++)
                        if (w2 >= 0 && w2 <= B) *(volatile int*)&g_lo[w2] = p + 1;
                if (p == P - 1)
                    for (int w2 = v + 1; w2 <= B; w2++)
                        *(volatile int*)&g_lo[w2] = P + 1;
            }
        }
        __syncthreads();

        const int sb0 = s_b0;
        const int sb1 = s_b1;
        const int qb  = s_qb;

        if (qb >= 0) {
            evalBatches(sb0, sb1, qb, base);
        } else {
            // fallback: restage queries QS batches at a time
            for (int bq = sb0; bq <= sb1; bq += QS) {
                const int nqw = min(QS, sb1 - bq + 1);
                __syncthreads();
                if (tid < nqw) s_aidx[tid] = agent_ptr[bq + tid];
                if (tid == 0) s_dstr = 1;
                __syncthreads();
                if (tid < nqw * 64) {
                    const int k  = tid >> 6;
                    const int qs = tid & 63;
                    const int qr = qs >> 5, qt = qs & 31;
                    const int a  = s_aidx[k];
                    float2 a2, b2;
                    if (qr == 0) {
                        const float2* ip = (const float2*)(infer_pos + (size_t)a * (IP_ROWS * 2));
                        a2 = ip[NUM_HIST + qt];
                        b2 = ip[NUM_HIST - 1 + qt];
                    } else {
                        const float2* ap = (const float2*)(agent_pos + (size_t)a * (L_ROWS * 2));
                        a2 = ap[(4 + qt) * INTERVAL];
                        b2 = ap[(3 + qt) * INTERVAL];
                    }
                    s_q[k][qs] = make_float4(a2.x, a2.y, a2.x - b2.x, a2.y - b2.y);
                }
                __syncthreads();
                evalBatches(bq, bq + nqw - 1, bq, base);
            }
        }

        // ---- completion publish for this sub-chunk ----
        __threadfence();
        __syncthreads();
        if (warp == 0) {
            for (int bb = sb0 + lane; bb <= sb1; bb += 32) {
                const int m = s_bnd[bb + 1] - s_bnd[bb];
                if (m > 0 && ((base + cnt >= c1) || (bb < s_nextb)))
                    atomicAdd(&g_fin[bb], 1);
            }
        }
        __syncthreads();
    }

    // ================= phase 2: per-batch wait (no global barrier) ==========
    if (bi < B) {
        if (tid == 0) {
            int lo1, hi1;
            while ((lo1 = *(volatile int*)&g_lo[bi])     == 0) { }
            while ((hi1 = *(volatile int*)&g_lo[bi + 1]) == 0) { }
            const int lo = lo1 - 1, hi = hi1 - 1;
            const int nexp = (hi > lo) ? ((hi - 1) / chunk - lo / chunk + 1) : 0;
            if (nexp > 0)
                while (*(volatile int*)&g_fin[bi] < nexp) { }
            __threadfence();            // acquire winners
            g_fin[bi] = 0;              // reset for next replay
        }
        __syncthreads();
        if (tid < 64) {
            const unsigned long long w = ~g_win[bi * 64 + tid];
            g_win[bi * 64 + tid] = 0;   // reset for next replay
            float prog = 0.0f;
            if ((unsigned)(w >> 32) < 0x7F800000u)
                prog = __uint_as_float((unsigned)w);
            #pragma unroll
            for (int o = 16; o > 0; o >>= 1)
                prog += __shfl_down_sync(0xFFFFFFFFu, prog, o);
            if (t == 0) s_sum[role] = prog;
        }
        __syncthreads();
        if (tid == 0)
            out[bi] = fminf(fmaxf(s_sum[0], 2.0f) / fmaxf(s_sum[1], 2.0f), 1.0f);
    }
}

extern "C" void kernel_launch(void* const* d_in, const int* in_sizes, int n_in,
                              void* d_out, int out_size)
{
    const int*   poly_batch    = (const int*)  d_in[0];
    const float* poly_pos      = (const float*)d_in[1];
    const float* poly_heading  = (const float*)d_in[2];
    const int*   edge_index    = (const int*)  d_in[3];
    const int*   on_route_mask = (const int*)  d_in[4];
    const int*   agent_ptr     = (const int*)  d_in[5];
    const float* infer_pos     = (const float*)d_in[6];
    const int*   agent_batch   = (const int*)  d_in[7];
    const float* agent_pos     = (const float*)d_in[8];
    float*       out           = (float*)      d_out;

    const int P  = in_sizes[0];
    const int NG = in_sizes[4];
    int B        = in_sizes[5] - 1;
    if (B > B_MAX) B = B_MAX;
    const int A  = in_sizes[7];
    const int agents_per = (B > 0) ? (A / B) : 1;

    int grid = 128;
    if (B > grid) grid = (B <= 148) ? B : 148;

    progress_reward_kernel<<<grid, TPB>>>(
        poly_batch, poly_pos, poly_heading, edge_index, on_route_mask,
        agent_ptr, infer_pos, agent_batch, agent_pos, out,
        P, NG, B, agents_per);
}